// round 1
// baseline (speedup 1.0000x reference)
#include <cuda_runtime.h>

// Problem constants (fixed by the reference)
#define NN 50000
#define EE 800000
#define DD 128
#define HH 128
#define GG 256

// Scratch (no allocs allowed — __device__ globals)
__device__ float g_deg[NN];
__device__ float g_dinv[NN];
__device__ float g_norm[EE];
__device__ float g_zw[(size_t)NN * HH];   // z @ W (pre-aggregation)
__device__ float g_agg[(size_t)NN * HH];  // scatter accumulator
__device__ float g_z1[(size_t)NN * HH];   // layer-1 output (needed for layer 2 + pooling)

// ---------------------------------------------------------------------------
// Degree / normalization
// ---------------------------------------------------------------------------
__global__ void k_init_deg() {
    int i = blockIdx.x * blockDim.x + threadIdx.x;
    if (i < NN) g_deg[i] = 1.0f;  // self-loop contributes 1 to deg[dst]
}

__global__ void k_deg_scatter(const int* __restrict__ dst) {
    int e = blockIdx.x * blockDim.x + threadIdx.x;
    if (e < EE) atomicAdd(&g_deg[dst[e]], 1.0f);
}

__global__ void k_dinv() {
    int i = blockIdx.x * blockDim.x + threadIdx.x;
    if (i < NN) g_dinv[i] = rsqrtf(g_deg[i]);  // deg >= 1 always (self-loops)
}

__global__ void k_norm(const int* __restrict__ src, const int* __restrict__ dst) {
    int e = blockIdx.x * blockDim.x + threadIdx.x;
    if (e < EE) g_norm[e] = g_dinv[src[e]] * g_dinv[dst[e]];
}

__global__ void k_zero_pool(float* __restrict__ out) {
    int i = blockIdx.x * blockDim.x + threadIdx.x;
    if (i < GG * 2 * HH) out[(size_t)NN * HH + i] = 0.0f;
}

// ---------------------------------------------------------------------------
// GEMM: zw = A @ W  (A: [NN,128], W: [128,128]); also zeroes agg for the layer.
// 128 threads (one per output column), 16 rows per block, x-tile in smem.
// ---------------------------------------------------------------------------
#define GEMM_ROWS 16
__global__ void __launch_bounds__(128) k_gemm(const float* __restrict__ A,
                                              const float* __restrict__ W) {
    __shared__ float xs[GEMM_ROWS][128];
    const int row0 = blockIdx.x * GEMM_ROWS;
    const int c = threadIdx.x;

#pragma unroll
    for (int r = 0; r < GEMM_ROWS; r++)
        xs[r][c] = A[(size_t)(row0 + r) * 128 + c];
    __syncthreads();

    float acc[GEMM_ROWS];
#pragma unroll
    for (int r = 0; r < GEMM_ROWS; r++) acc[r] = 0.0f;

#pragma unroll 4
    for (int k = 0; k < 128; k++) {
        float w = W[(size_t)k * 128 + c];
#pragma unroll
        for (int r = 0; r < GEMM_ROWS; r++)
            acc[r] = fmaf(xs[r][k], w, acc[r]);
    }

#pragma unroll
    for (int r = 0; r < GEMM_ROWS; r++) {
        size_t o = (size_t)(row0 + r) * 128 + c;
        g_zw[o] = acc[r];
        g_agg[o] = 0.0f;
    }
}

// ---------------------------------------------------------------------------
// Edge scatter: agg[dst] += norm[e] * zw[src].  One warp per edge, float4 loads,
// scalar atomicAdds (no return -> RED).
// ---------------------------------------------------------------------------
__global__ void __launch_bounds__(128) k_scatter(const int* __restrict__ src,
                                                 const int* __restrict__ dst) {
    int e = blockIdx.x * 4 + (threadIdx.x >> 5);
    if (e >= EE) return;
    int lane = threadIdx.x & 31;
    int s = src[e];
    int d = dst[e];
    float w = g_norm[e];
    float4 v = reinterpret_cast<const float4*>(&g_zw[(size_t)s * 128])[lane];
    float* a = &g_agg[(size_t)d * 128 + lane * 4];
    atomicAdd(a + 0, w * v.x);
    atomicAdd(a + 1, w * v.y);
    atomicAdd(a + 2, w * v.z);
    atomicAdd(a + 3, w * v.w);
}

// ---------------------------------------------------------------------------
// Epilogue: z = PReLU(agg + dinv^2 * zw + b); write z; atomic-add into pool.
// One block per node, 128 threads (one per channel).
// ---------------------------------------------------------------------------
__global__ void __launch_bounds__(128) k_epilogue(const float* __restrict__ b,
                                                  const float* __restrict__ alpha,
                                                  const int* __restrict__ batch,
                                                  float* __restrict__ zout,
                                                  float* __restrict__ pool,
                                                  int pool_off) {
    int i = blockIdx.x;
    int c = threadIdx.x;
    float s = g_dinv[i];
    s = s * s;  // self-loop norm = dinv^2
    size_t o = (size_t)i * 128 + c;
    float v = g_agg[o] + s * g_zw[o] + b[c];
    v = (v > 0.0f) ? v : alpha[c] * v;
    zout[o] = v;
    atomicAdd(&pool[(size_t)batch[i] * (2 * HH) + pool_off + c], v);
}

// ---------------------------------------------------------------------------
// Launch
// ---------------------------------------------------------------------------
extern "C" void kernel_launch(void* const* d_in, const int* in_sizes, int n_in,
                              void* d_out, int out_size) {
    const float* x     = (const float*)d_in[0];
    const int*   eidx  = (const int*)d_in[1];
    const int*   batch = (const int*)d_in[2];
    const float* W1    = (const float*)d_in[3];
    const float* b1    = (const float*)d_in[4];
    const float* W2    = (const float*)d_in[5];
    const float* b2    = (const float*)d_in[6];
    const float* alpha = (const float*)d_in[7];

    const int* src = eidx;       // edge_index[0]
    const int* dst = eidx + EE;  // edge_index[1]

    float* out  = (float*)d_out;                 // z: [NN*HH]
    float* pool = out + (size_t)NN * HH;         // g: [GG, 2*HH]

    // Normalization (norm reused by both layers)
    k_init_deg<<<(NN + 255) / 256, 256>>>();
    k_deg_scatter<<<(EE + 255) / 256, 256>>>(dst);
    k_dinv<<<(NN + 255) / 256, 256>>>();
    k_norm<<<(EE + 255) / 256, 256>>>(src, dst);
    k_zero_pool<<<(GG * 2 * HH + 255) / 256, 256>>>(out);

    // Layer 1
    k_gemm<<<NN / GEMM_ROWS + (NN % GEMM_ROWS ? 1 : 0), 128>>>(x, W1);
    k_scatter<<<(EE + 3) / 4, 128>>>(src, dst);
    float* z1;
    cudaGetSymbolAddress((void**)&z1, g_z1);
    k_epilogue<<<NN, 128>>>(b1, alpha, batch, z1, pool, 0);

    // Layer 2
    k_gemm<<<NN / GEMM_ROWS + (NN % GEMM_ROWS ? 1 : 0), 128>>>(z1, W2);
    k_scatter<<<(EE + 3) / 4, 128>>>(src, dst);
    k_epilogue<<<NN, 128>>>(b2, alpha, batch, out, pool, HH);
}

// round 2
// speedup vs baseline: 1.8929x; 1.8929x over previous
#include <cuda_runtime.h>

#define NN 50000
#define EE 800000
#define DD 128
#define HH 128
#define GG 256

// Scratch (__device__ globals — no allocs allowed)
__device__ int   g_indeg[NN];
__device__ float g_dinv[NN];
__device__ int   g_row_off[NN + 1];
__device__ int   g_cursor[NN];
__device__ int   g_csr_src[EE];
__device__ float g_zws[(size_t)NN * HH];  // dinv[i] * (z @ W)[i]
__device__ float g_z1[(size_t)NN * HH];   // layer-1 output

// ---------------------------------------------------------------------------
// Setup: degrees, dinv, CSR by dst
// ---------------------------------------------------------------------------
__global__ void k_indeg_zero() {
    int i = blockIdx.x * blockDim.x + threadIdx.x;
    if (i < NN) g_indeg[i] = 0;
}

__global__ void k_deg(const int* __restrict__ dst) {
    int e = blockIdx.x * blockDim.x + threadIdx.x;
    if (e < EE) atomicAdd(&g_indeg[dst[e]], 1);
}

__global__ void k_dinv() {
    int i = blockIdx.x * blockDim.x + threadIdx.x;
    if (i < NN) g_dinv[i] = rsqrtf((float)g_indeg[i] + 1.0f);  // +1 self-loop
}

// Single-block exclusive prefix sum over indeg -> row_off, cursor
__global__ void __launch_bounds__(1024) k_scan() {
    __shared__ int partial[1024];
    const int per = (NN + 1023) / 1024;  // 49
    int t = threadIdx.x;
    int base = t * per;
    int s = 0;
    for (int i = 0; i < per; i++) {
        int idx = base + i;
        if (idx < NN) s += g_indeg[idx];
    }
    partial[t] = s;
    __syncthreads();
    for (int off = 1; off < 1024; off <<= 1) {
        int v = (t >= off) ? partial[t - off] : 0;
        __syncthreads();
        partial[t] += v;
        __syncthreads();
    }
    int excl = (t == 0) ? 0 : partial[t - 1];
    for (int i = 0; i < per; i++) {
        int idx = base + i;
        if (idx < NN) {
            int d = g_indeg[idx];
            g_row_off[idx] = excl;
            g_cursor[idx] = excl;
            excl += d;
        }
    }
    if (t == 1023) g_row_off[NN] = excl;
}

__global__ void k_fill(const int* __restrict__ src, const int* __restrict__ dst) {
    int e = blockIdx.x * blockDim.x + threadIdx.x;
    if (e < EE) {
        int p = atomicAdd(&g_cursor[dst[e]], 1);
        g_csr_src[p] = src[e];
    }
}

__global__ void k_zero_pool(float* __restrict__ out) {
    int i = blockIdx.x * blockDim.x + threadIdx.x;
    if (i < GG * 2 * HH) out[(size_t)NN * HH + i] = 0.0f;
}

// ---------------------------------------------------------------------------
// GEMM: g_zws = dinv[:,None] * (A @ W).  Block: 16 rows x 128 cols, 128 thr,
// each thread 4x4 register tile, float4 loads everywhere.
// ---------------------------------------------------------------------------
#define GR 16
__global__ void __launch_bounds__(128) k_gemm(const float* __restrict__ A,
                                              const float* __restrict__ W) {
    __shared__ float4 xs[GR][32];  // [row][k4]
    const int row0 = blockIdx.x * GR;
    const int t = threadIdx.x;

    const float4* A4 = (const float4*)A;
    for (int i = t; i < GR * 32; i += 128) {
        int r = i >> 5, k4 = i & 31;
        xs[r][k4] = A4[(size_t)(row0 + r) * 32 + k4];
    }
    __syncthreads();

    const int cg = t & 31;  // cols 4cg..4cg+3
    const int rg = t >> 5;  // rows 4rg..4rg+3

    float acc[4][4];
#pragma unroll
    for (int r = 0; r < 4; r++)
#pragma unroll
        for (int c = 0; c < 4; c++) acc[r][c] = 0.0f;

    for (int k4 = 0; k4 < 32; k4++) {
        float a[4][4];  // [r][kk]
#pragma unroll
        for (int r = 0; r < 4; r++) {
            float4 av = xs[4 * rg + r][k4];
            a[r][0] = av.x; a[r][1] = av.y; a[r][2] = av.z; a[r][3] = av.w;
        }
        float w[4][4];  // [kk][c]
#pragma unroll
        for (int kk = 0; kk < 4; kk++) {
            float4 wv = __ldg((const float4*)&W[(size_t)(4 * k4 + kk) * 128 + 4 * cg]);
            w[kk][0] = wv.x; w[kk][1] = wv.y; w[kk][2] = wv.z; w[kk][3] = wv.w;
        }
#pragma unroll
        for (int r = 0; r < 4; r++)
#pragma unroll
            for (int kk = 0; kk < 4; kk++)
#pragma unroll
                for (int c = 0; c < 4; c++)
                    acc[r][c] = fmaf(a[r][kk], w[kk][c], acc[r][c]);
    }

#pragma unroll
    for (int r = 0; r < 4; r++) {
        int row = row0 + 4 * rg + r;
        float di = g_dinv[row];
        float4 o;
        o.x = di * acc[r][0]; o.y = di * acc[r][1];
        o.z = di * acc[r][2]; o.w = di * acc[r][3];
        ((float4*)g_zws)[(size_t)row * 32 + cg] = o;
    }
}

// ---------------------------------------------------------------------------
// Gather + epilogue: one warp per dst node.
// h[d] = PReLU(dinv[d]*(zws[d] + sum_{src in CSR[d]} zws[src]) + b)
// write h; atomic-add into pool[batch[d]].
// ---------------------------------------------------------------------------
__global__ void __launch_bounds__(128) k_gather(const float* __restrict__ b,
                                                const float* __restrict__ alpha,
                                                const int* __restrict__ batch,
                                                float* __restrict__ zout,
                                                float* __restrict__ pool,
                                                int pool_off) {
    int d = blockIdx.x * 4 + (threadIdx.x >> 5);
    if (d >= NN) return;
    int lane = threadIdx.x & 31;

    const float4* zws4 = (const float4*)g_zws;
    int beg = g_row_off[d];
    int end = g_row_off[d + 1];

    float4 acc = __ldg(&zws4[(size_t)d * 32 + lane]);  // self-loop term
    float4 acc2 = make_float4(0.f, 0.f, 0.f, 0.f);

    int e = beg;
    for (; e + 1 < end; e += 2) {
        int s0 = g_csr_src[e];
        int s1 = g_csr_src[e + 1];
        float4 v0 = __ldg(&zws4[(size_t)s0 * 32 + lane]);
        float4 v1 = __ldg(&zws4[(size_t)s1 * 32 + lane]);
        acc.x += v0.x; acc.y += v0.y; acc.z += v0.z; acc.w += v0.w;
        acc2.x += v1.x; acc2.y += v1.y; acc2.z += v1.z; acc2.w += v1.w;
    }
    if (e < end) {
        int s0 = g_csr_src[e];
        float4 v0 = __ldg(&zws4[(size_t)s0 * 32 + lane]);
        acc.x += v0.x; acc.y += v0.y; acc.z += v0.z; acc.w += v0.w;
    }
    acc.x += acc2.x; acc.y += acc2.y; acc.z += acc2.z; acc.w += acc2.w;

    float di = g_dinv[d];
    float4 bb = __ldg(&((const float4*)b)[lane]);
    float4 al = __ldg(&((const float4*)alpha)[lane]);
    float4 h;
    h.x = di * acc.x + bb.x; h.x = (h.x > 0.f) ? h.x : al.x * h.x;
    h.y = di * acc.y + bb.y; h.y = (h.y > 0.f) ? h.y : al.y * h.y;
    h.z = di * acc.z + bb.z; h.z = (h.z > 0.f) ? h.z : al.z * h.z;
    h.w = di * acc.w + bb.w; h.w = (h.w > 0.f) ? h.w : al.w * h.w;

    ((float4*)zout)[(size_t)d * 32 + lane] = h;

    float* p = &pool[(size_t)batch[d] * (2 * HH) + pool_off + lane * 4];
    atomicAdd(p + 0, h.x);
    atomicAdd(p + 1, h.y);
    atomicAdd(p + 2, h.z);
    atomicAdd(p + 3, h.w);
}

// ---------------------------------------------------------------------------
extern "C" void kernel_launch(void* const* d_in, const int* in_sizes, int n_in,
                              void* d_out, int out_size) {
    const float* x     = (const float*)d_in[0];
    const int*   eidx  = (const int*)d_in[1];
    const int*   batch = (const int*)d_in[2];
    const float* W1    = (const float*)d_in[3];
    const float* b1    = (const float*)d_in[4];
    const float* W2    = (const float*)d_in[5];
    const float* b2    = (const float*)d_in[6];
    const float* alpha = (const float*)d_in[7];

    const int* src = eidx;       // edge_index[0]
    const int* dst = eidx + EE;  // edge_index[1]

    float* out  = (float*)d_out;
    float* pool = out + (size_t)NN * HH;

    // Setup (norm structure reused by both layers)
    k_indeg_zero<<<(NN + 255) / 256, 256>>>();
    k_deg<<<(EE + 255) / 256, 256>>>(dst);
    k_dinv<<<(NN + 255) / 256, 256>>>();
    k_scan<<<1, 1024>>>();
    k_fill<<<(EE + 255) / 256, 256>>>(src, dst);
    k_zero_pool<<<(GG * 2 * HH + 255) / 256, 256>>>(out);

    float* z1;
    cudaGetSymbolAddress((void**)&z1, g_z1);

    // Layer 1
    k_gemm<<<NN / GR + (NN % GR ? 1 : 0), 128>>>(x, W1);
    k_gather<<<(NN + 3) / 4, 128>>>(b1, alpha, batch, z1, pool, 0);

    // Layer 2
    k_gemm<<<NN / GR + (NN % GR ? 1 : 0), 128>>>(z1, W2);
    k_gather<<<(NN + 3) / 4, 128>>>(b2, alpha, batch, out, pool, HH);
}

// round 3
// speedup vs baseline: 2.4092x; 1.2727x over previous
#include <cuda_runtime.h>

#define NN 50000
#define EE 800000
#define DD 128
#define HH 128
#define GG 256

typedef unsigned long long ull;

// Scratch (__device__ globals — no allocs allowed)
__device__ int   g_indeg[NN];
__device__ float g_dinv[NN];
__device__ int   g_row_off[NN + 1];
__device__ int   g_cursor[NN];
__device__ int   g_csr_src[EE];
__device__ float g_zws[(size_t)NN * HH];  // dinv[i] * (z @ W)[i]
__device__ float g_z1[(size_t)NN * HH];   // layer-1 output

#define SCAN_B 256
#define SCAN_NB ((NN + SCAN_B - 1) / SCAN_B)  // 196
__device__ int g_bsum[SCAN_NB];
__device__ int g_boff[SCAN_NB];

// f32x2 packed FMA (Blackwell FFMA2 — only reachable via PTX)
#define FFMA2(d, a, b) \
    asm("fma.rn.f32x2 %0, %1, %2, %0;" : "+l"(d) : "l"(a), "l"(b))

// ---------------------------------------------------------------------------
// Setup: degrees, dinv
// ---------------------------------------------------------------------------
__global__ void k_indeg_zero() {
    int i = blockIdx.x * blockDim.x + threadIdx.x;
    if (i < NN) g_indeg[i] = 0;
}

__global__ void k_deg(const int* __restrict__ dst) {
    int e = blockIdx.x * blockDim.x + threadIdx.x;
    if (e < EE) atomicAdd(&g_indeg[dst[e]], 1);
}

__global__ void k_dinv() {
    int i = blockIdx.x * blockDim.x + threadIdx.x;
    if (i < NN) g_dinv[i] = rsqrtf((float)g_indeg[i] + 1.0f);  // +1 self-loop
}

// ---------------------------------------------------------------------------
// Hierarchical exclusive scan of indeg -> row_off, cursor
// ---------------------------------------------------------------------------
__global__ void __launch_bounds__(SCAN_B) k_scan_block() {
    __shared__ int sh[SCAN_B];
    int i = blockIdx.x * SCAN_B + threadIdx.x;
    int v = (i < NN) ? g_indeg[i] : 0;
    sh[threadIdx.x] = v;
    __syncthreads();
    for (int off = SCAN_B / 2; off > 0; off >>= 1) {
        if (threadIdx.x < off) sh[threadIdx.x] += sh[threadIdx.x + off];
        __syncthreads();
    }
    if (threadIdx.x == 0) g_bsum[blockIdx.x] = sh[0];
}

__global__ void __launch_bounds__(SCAN_B) k_scan_top() {
    __shared__ int sh[SCAN_B];
    int t = threadIdx.x;
    int v = (t < SCAN_NB) ? g_bsum[t] : 0;
    sh[t] = v;
    __syncthreads();
    for (int off = 1; off < SCAN_B; off <<= 1) {
        int u = (t >= off) ? sh[t - off] : 0;
        __syncthreads();
        sh[t] += u;
        __syncthreads();
    }
    if (t < SCAN_NB) g_boff[t] = sh[t] - v;  // exclusive
    if (t == 0) g_row_off[NN] = EE;
}

__global__ void __launch_bounds__(SCAN_B) k_scan_fill() {
    __shared__ int sh[SCAN_B];
    int i = blockIdx.x * SCAN_B + threadIdx.x;
    int t = threadIdx.x;
    int v = (i < NN) ? g_indeg[i] : 0;
    sh[t] = v;
    __syncthreads();
    for (int off = 1; off < SCAN_B; off <<= 1) {
        int u = (t >= off) ? sh[t - off] : 0;
        __syncthreads();
        sh[t] += u;
        __syncthreads();
    }
    if (i < NN) {
        int excl = g_boff[blockIdx.x] + sh[t] - v;
        g_row_off[i] = excl;
        g_cursor[i] = excl;
    }
}

__global__ void k_fill(const int* __restrict__ src, const int* __restrict__ dst) {
    int e = blockIdx.x * blockDim.x + threadIdx.x;
    if (e < EE) {
        int p = atomicAdd(&g_cursor[dst[e]], 1);
        g_csr_src[p] = src[e];
    }
}

__global__ void k_zero_pool(float* __restrict__ out) {
    int i = blockIdx.x * blockDim.x + threadIdx.x;
    if (i < GG * 2 * HH) out[(size_t)NN * HH + i] = 0.0f;
}

// ---------------------------------------------------------------------------
// GEMM: g_zws = dinv[:,None] * (A @ W)  via packed f32x2 FFMA2.
// Block: 16 rows x 128 cols, 128 threads, 4x4 tile per thread.
// A-tile pre-splatted in smem as {a,a} so each operand is one LDS.64 broadcast.
// ---------------------------------------------------------------------------
#define GR 16
__global__ void __launch_bounds__(128) k_gemm(const float* __restrict__ A,
                                              const float* __restrict__ W) {
    __shared__ float2 xs2[GR][128];  // splatted: xs2[r][k] = {A[r][k], A[r][k]}
    const int row0 = blockIdx.x * GR;
    const int t = threadIdx.x;

    const float4* A4 = (const float4*)A;
    for (int i = t; i < GR * 32; i += 128) {
        int r = i >> 5, k4 = i & 31;
        float4 v = A4[(size_t)(row0 + r) * 32 + k4];
        xs2[r][4 * k4 + 0] = make_float2(v.x, v.x);
        xs2[r][4 * k4 + 1] = make_float2(v.y, v.y);
        xs2[r][4 * k4 + 2] = make_float2(v.z, v.z);
        xs2[r][4 * k4 + 3] = make_float2(v.w, v.w);
    }
    __syncthreads();

    const int cg = t & 31;  // this thread's cols: 4cg..4cg+3
    const int rg = t >> 5;  // this thread's rows: 4rg..4rg+3

    ull acc[4][2];
#pragma unroll
    for (int r = 0; r < 4; r++) { acc[r][0] = 0ULL; acc[r][1] = 0ULL; }

#pragma unroll 4
    for (int k = 0; k < 128; k++) {
        ulonglong2 wv = *(const ulonglong2*)&W[(size_t)k * 128 + 4 * cg];
#pragma unroll
        for (int r = 0; r < 4; r++) {
            ull a2 = *(const ull*)&xs2[4 * rg + r][k];
            FFMA2(acc[r][0], a2, wv.x);
            FFMA2(acc[r][1], a2, wv.y);
        }
    }

#pragma unroll
    for (int r = 0; r < 4; r++) {
        int row = row0 + 4 * rg + r;
        float di = g_dinv[row];
        float2 p0, p1;
        *(ull*)&p0 = acc[r][0];
        *(ull*)&p1 = acc[r][1];
        float4 o;
        o.x = di * p0.x; o.y = di * p0.y;
        o.z = di * p1.x; o.w = di * p1.y;
        ((float4*)g_zws)[(size_t)row * 32 + cg] = o;
    }
}

// ---------------------------------------------------------------------------
// Gather + epilogue: one warp per dst node.
// h[d] = PReLU(dinv[d]*(zws[d] + sum_{src in CSR[d]} zws[src]) + b)
// ---------------------------------------------------------------------------
__global__ void __launch_bounds__(128) k_gather(const float* __restrict__ b,
                                                const float* __restrict__ alpha,
                                                const int* __restrict__ batch,
                                                float* __restrict__ zout,
                                                float* __restrict__ pool,
                                                int pool_off) {
    int d = blockIdx.x * 4 + (threadIdx.x >> 5);
    if (d >= NN) return;
    int lane = threadIdx.x & 31;

    const float4* zws4 = (const float4*)g_zws;
    int beg = g_row_off[d];
    int end = g_row_off[d + 1];

    float4 acc = __ldg(&zws4[(size_t)d * 32 + lane]);  // self-loop term
    float4 acc2 = make_float4(0.f, 0.f, 0.f, 0.f);

    int e = beg;
    for (; e + 1 < end; e += 2) {
        int s0 = g_csr_src[e];
        int s1 = g_csr_src[e + 1];
        float4 v0 = __ldg(&zws4[(size_t)s0 * 32 + lane]);
        float4 v1 = __ldg(&zws4[(size_t)s1 * 32 + lane]);
        acc.x += v0.x; acc.y += v0.y; acc.z += v0.z; acc.w += v0.w;
        acc2.x += v1.x; acc2.y += v1.y; acc2.z += v1.z; acc2.w += v1.w;
    }
    if (e < end) {
        int s0 = g_csr_src[e];
        float4 v0 = __ldg(&zws4[(size_t)s0 * 32 + lane]);
        acc.x += v0.x; acc.y += v0.y; acc.z += v0.z; acc.w += v0.w;
    }
    acc.x += acc2.x; acc.y += acc2.y; acc.z += acc2.z; acc.w += acc2.w;

    float di = g_dinv[d];
    float4 bb = __ldg(&((const float4*)b)[lane]);
    float4 al = __ldg(&((const float4*)alpha)[lane]);
    float4 h;
    h.x = di * acc.x + bb.x; h.x = (h.x > 0.f) ? h.x : al.x * h.x;
    h.y = di * acc.y + bb.y; h.y = (h.y > 0.f) ? h.y : al.y * h.y;
    h.z = di * acc.z + bb.z; h.z = (h.z > 0.f) ? h.z : al.z * h.z;
    h.w = di * acc.w + bb.w; h.w = (h.w > 0.f) ? h.w : al.w * h.w;

    ((float4*)zout)[(size_t)d * 32 + lane] = h;

    float* p = &pool[(size_t)batch[d] * (2 * HH) + pool_off + lane * 4];
    atomicAdd(p + 0, h.x);
    atomicAdd(p + 1, h.y);
    atomicAdd(p + 2, h.z);
    atomicAdd(p + 3, h.w);
}

// ---------------------------------------------------------------------------
extern "C" void kernel_launch(void* const* d_in, const int* in_sizes, int n_in,
                              void* d_out, int out_size) {
    const float* x     = (const float*)d_in[0];
    const int*   eidx  = (const int*)d_in[1];
    const int*   batch = (const int*)d_in[2];
    const float* W1    = (const float*)d_in[3];
    const float* b1    = (const float*)d_in[4];
    const float* W2    = (const float*)d_in[5];
    const float* b2    = (const float*)d_in[6];
    const float* alpha = (const float*)d_in[7];

    const int* src = eidx;       // edge_index[0]
    const int* dst = eidx + EE;  // edge_index[1]

    float* out  = (float*)d_out;
    float* pool = out + (size_t)NN * HH;

    // Setup (structure reused by both layers)
    k_indeg_zero<<<(NN + 255) / 256, 256>>>();
    k_deg<<<(EE + 255) / 256, 256>>>(dst);
    k_dinv<<<(NN + 255) / 256, 256>>>();
    k_scan_block<<<SCAN_NB, SCAN_B>>>();
    k_scan_top<<<1, SCAN_B>>>();
    k_scan_fill<<<SCAN_NB, SCAN_B>>>();
    k_fill<<<(EE + 255) / 256, 256>>>(src, dst);
    k_zero_pool<<<(GG * 2 * HH + 255) / 256, 256>>>(out);

    float* z1;
    cudaGetSymbolAddress((void**)&z1, g_z1);

    // Layer 1
    k_gemm<<<NN / GR + (NN % GR ? 1 : 0), 128>>>(x, W1);
    k_gather<<<(NN + 3) / 4, 128>>>(b1, alpha, batch, z1, pool, 0);

    // Layer 2
    k_gemm<<<NN / GR + (NN % GR ? 1 : 0), 128>>>(z1, W2);
    k_gather<<<(NN + 3) / 4, 128>>>(b2, alpha, batch, out, pool, HH);
}